// round 4
// baseline (speedup 1.0000x reference)
#include <cuda_runtime.h>
#include <math.h>

// Problem constants
#define B_  256
#define T_  1024
#define I_  3
#define H_  128
#define O_  3

#define NTHREADS 160   // 4 compute warps + 1 outproj reducer warp

// ---------------------------------------------------------------------------
// Fast tanh, single-ended clamp: tanh(x) = 1 - 2/(1 + e^{2x}).
// e^{2x} = ex2.approx(x * 2*log2(e)). For x very negative ex2 -> 0 -> -1 (ok).
// Upper clamp keeps ex2 finite (avoids inf/inf). Chain ~48 cyc.
// ---------------------------------------------------------------------------
__device__ __forceinline__ float fast_tanh(float x) {
    float u = fminf(x * 2.885390081777927f, 80.0f);   // 2*log2(e)*x, clamped
    float e;
    asm("ex2.approx.f32 %0, %1;" : "=f"(e) : "f"(u)); // e = exp(2x)
    float rd;
    asm("rcp.approx.f32 %0, %1;" : "=f"(rd) : "f"(1.0f + e));
    return fmaf(-2.0f, rd, 1.0f);
}

// ---------------------------------------------------------------------------
// Fused recurrent + output-projection kernel.
// One block per batch element. Threads 0..127 ("main"): hidden unit j, W_hh
// row j in 128 registers, double-buffered h in smem, one barrier per step.
// Threads 128..159 ("reducer" warp): one step behind, dot-products the
// buffer the main warps are *reading* (h_{t-1}) against W_out -> out[b][t-1].
// The shared per-step barrier is the only synchronization.
// ---------------------------------------------------------------------------
__global__ void __launch_bounds__(NTHREADS, 2)
rnn_fused_kernel(const float* __restrict__ inputs,   // [B, T, I]
                 const float* __restrict__ W_ih,     // [H, I]
                 const float* __restrict__ W_hh,     // [H, H]
                 const float* __restrict__ b_ih,     // [H]
                 const float* __restrict__ b_hh,     // [H]
                 const float* __restrict__ h0,       // [1, H]
                 const float* __restrict__ W_out,    // [O, H]
                 const float* __restrict__ b_out,    // [O]
                 float* __restrict__ out,            // [B, T, O]
                 float* __restrict__ hiddens)        // [B, T, H]
{
    const int b   = blockIdx.x;
    const int tid = threadIdx.x;

    __shared__ float hbuf[2][H_];

    if (tid < H_) {
        // ----- main compute threads -----
        const int j = tid;

        float w[H_];
        const float4* wrow = reinterpret_cast<const float4*>(W_hh + j * H_);
#pragma unroll
        for (int kk = 0; kk < H_ / 4; ++kk) {
            float4 v = wrow[kk];
            w[4 * kk + 0] = v.x;
            w[4 * kk + 1] = v.y;
            w[4 * kk + 2] = v.z;
            w[4 * kk + 3] = v.w;
        }

        const float wi0  = W_ih[j * I_ + 0];
        const float wi1  = W_ih[j * I_ + 1];
        const float wi2  = W_ih[j * I_ + 2];
        const float bias = b_ih[j] + b_hh[j];

        hbuf[0][j] = h0[j];
        __syncthreads();

        const float* inb  = inputs + (size_t)b * T_ * I_;
        float*       hout = hiddens + (size_t)b * T_ * H_;

        float x0 = inb[0], x1 = inb[1], x2 = inb[2];

        int cur = 0;
#pragma unroll 1
        for (int t = 0; t < T_; ++t) {
            float acc = fmaf(x0, wi0, fmaf(x1, wi1, fmaf(x2, wi2, bias)));

            // prefetch next x
            {
                const int tn = (t + 1 < T_) ? (t + 1) : (T_ - 1);
                const float* nx = inb + tn * I_;
                x0 = nx[0]; x1 = nx[1]; x2 = nx[2];
            }

            float a0 = 0.f, a1 = 0.f, a2 = 0.f, a3 = 0.f;
            const float4* h4 = reinterpret_cast<const float4*>(hbuf[cur]);
#pragma unroll
            for (int kk = 0; kk < H_ / 4; ++kk) {
                float4 hv = h4[kk];
                a0 = fmaf(hv.x, w[4 * kk + 0], a0);
                a1 = fmaf(hv.y, w[4 * kk + 1], a1);
                a2 = fmaf(hv.z, w[4 * kk + 2], a2);
                a3 = fmaf(hv.w, w[4 * kk + 3], a3);
            }
            acc += (a0 + a1) + (a2 + a3);

            const float hn = fast_tanh(acc);
            const int nxt = cur ^ 1;
            hbuf[nxt][j] = hn;
            hout[t * H_ + j] = hn;
            cur = nxt;
            __syncthreads();
        }
        // final barrier partner for the reducer's last step is below (none
        // needed: main warps are done writing; reducer only reads hbuf).
    } else {
        // ----- reducer warp: output projection, one step behind -----
        const int lane = tid - H_;   // 0..31

        const float4 w0 = reinterpret_cast<const float4*>(W_out + 0 * H_)[lane];
        const float4 w1 = reinterpret_cast<const float4*>(W_out + 1 * H_)[lane];
        const float4 w2 = reinterpret_cast<const float4*>(W_out + 2 * H_)[lane];
        const float bo0 = b_out[0], bo1 = b_out[1], bo2 = b_out[2];

        float* ob = out + (size_t)b * T_ * O_;

        __syncthreads();   // pairs with main warps' init barrier

        int cur = 0;
#pragma unroll 1
        for (int t = 0; t < T_; ++t) {
            // hbuf[cur] currently holds h_{t-1} (the buffer main warps read).
            // For t == 0 it holds h_init, which is not an output -> skip.
            if (t > 0) {
                const float4 hv = reinterpret_cast<const float4*>(hbuf[cur])[lane];
                float s0 = hv.x * w0.x + hv.y * w0.y + hv.z * w0.z + hv.w * w0.w;
                float s1 = hv.x * w1.x + hv.y * w1.y + hv.z * w1.z + hv.w * w1.w;
                float s2 = hv.x * w2.x + hv.y * w2.y + hv.z * w2.z + hv.w * w2.w;
#pragma unroll
                for (int off = 16; off > 0; off >>= 1) {
                    s0 += __shfl_down_sync(0xffffffffu, s0, off);
                    s1 += __shfl_down_sync(0xffffffffu, s1, off);
                    s2 += __shfl_down_sync(0xffffffffu, s2, off);
                }
                if (lane == 0) {
                    float* o = ob + (size_t)(t - 1) * O_;
                    o[0] = s0 + bo0;
                    o[1] = s1 + bo1;
                    o[2] = s2 + bo2;
                }
            }
            cur ^= 1;
            __syncthreads();
        }

        // Final step: hbuf[cur] now holds h_{T-1}; main warps are finished.
        {
            const float4 hv = reinterpret_cast<const float4*>(hbuf[cur])[lane];
            float s0 = hv.x * w0.x + hv.y * w0.y + hv.z * w0.z + hv.w * w0.w;
            float s1 = hv.x * w1.x + hv.y * w1.y + hv.z * w1.z + hv.w * w1.w;
            float s2 = hv.x * w2.x + hv.y * w2.y + hv.z * w2.z + hv.w * w2.w;
#pragma unroll
            for (int off = 16; off > 0; off >>= 1) {
                s0 += __shfl_down_sync(0xffffffffu, s0, off);
                s1 += __shfl_down_sync(0xffffffffu, s1, off);
                s2 += __shfl_down_sync(0xffffffffu, s2, off);
            }
            if (lane == 0) {
                float* o = ob + (size_t)(T_ - 1) * O_;
                o[0] = s0 + bo0;
                o[1] = s1 + bo1;
                o[2] = s2 + bo2;
            }
        }
    }
}

// ---------------------------------------------------------------------------
// kernel_launch
// ---------------------------------------------------------------------------
extern "C" void kernel_launch(void* const* d_in, const int* in_sizes, int n_in,
                              void* d_out, int out_size)
{
    const float* inputs = (const float*)d_in[0];
    const float* W_ih   = (const float*)d_in[1];
    const float* W_hh   = (const float*)d_in[2];
    const float* b_ih   = (const float*)d_in[3];
    const float* b_hh   = (const float*)d_in[4];
    const float* h0     = (const float*)d_in[5];
    const float* W_out  = (const float*)d_in[6];
    const float* b_out  = (const float*)d_in[7];

    float* out     = (float*)d_out;                        // [B,T,O]
    float* hiddens = (float*)d_out + (size_t)B_ * T_ * O_; // [B,T,H]

    rnn_fused_kernel<<<B_, NTHREADS>>>(inputs, W_ih, W_hh, b_ih, b_hh, h0,
                                       W_out, b_out, out, hiddens);
}

// round 5
// speedup vs baseline: 1.0312x; 1.0312x over previous
#include <cuda_runtime.h>
#include <math.h>

// Problem constants
#define B_  256
#define T_  1024
#define I_  3
#define H_  128
#define O_  3

// ---------------------------------------------------------------------------
// Fast tanh: tanh(x) = 1 - 2/(1 + e^{2x}) via ex2.approx + rcp.approx.
// Rel err ~1e-6 (proven over 1024-step recurrence: end-to-end 5e-7).
// ---------------------------------------------------------------------------
__device__ __forceinline__ float fast_tanh(float x) {
    float u = fminf(x * 2.885390081777927f, 80.0f);   // 2*log2(e)*x, clamped
    float e;
    asm("ex2.approx.f32 %0, %1;" : "=f"(e) : "f"(u));
    float rd;
    asm("rcp.approx.f32 %0, %1;" : "=f"(rd) : "f"(1.0f + e));
    return fmaf(-2.0f, rd, 1.0f);
}

// Named barrier over 128 threads (4 warps). Warps of one half only.
#define HALF_BAR(id) asm volatile("bar.sync %0, 128;" :: "r"(id) : "memory")

// ---------------------------------------------------------------------------
// Recurrent kernel: 128 blocks x 256 threads, 2 batch elements per block.
// half = tid>>7 selects the batch; j = tid&127 is the hidden unit.
// Warps 0-3 (half 0) and warps 4-7 (half 1) each span SMSPs 0-3, so every
// SMSP carries one warp of each half. The halves synchronize on SEPARATE
// named barriers, so when one half sits in its serial tanh/barrier tail the
// other half's FFMAs fill the issue slots. Uniform 1 block/SM (grid 128).
// ---------------------------------------------------------------------------
__global__ void __launch_bounds__(256, 1)
rnn_recurrent_kernel(const float* __restrict__ inputs,   // [B, T, I]
                     const float* __restrict__ W_ih,     // [H, I]
                     const float* __restrict__ W_hh,     // [H, H]
                     const float* __restrict__ b_ih,     // [H]
                     const float* __restrict__ b_hh,     // [H]
                     const float* __restrict__ h0,       // [1, H]
                     float* __restrict__ hiddens)        // [B, T, H]
{
    const int tid  = threadIdx.x;
    const int half = tid >> 7;          // 0/1: batch within block
    const int j    = tid & (H_ - 1);    // hidden unit
    const int b    = 2 * blockIdx.x + half;
    const int bar  = 1 + half;          // named barrier id for this half

    __shared__ float hbuf[2][2][H_];    // [buffer][half][j]

    // W_hh row j -> 128 registers
    float w[H_];
    const float4* wrow = reinterpret_cast<const float4*>(W_hh + j * H_);
#pragma unroll
    for (int kk = 0; kk < H_ / 4; ++kk) {
        float4 v = wrow[kk];
        w[4 * kk + 0] = v.x;
        w[4 * kk + 1] = v.y;
        w[4 * kk + 2] = v.z;
        w[4 * kk + 3] = v.w;
    }

    const float wi0  = W_ih[j * I_ + 0];
    const float wi1  = W_ih[j * I_ + 1];
    const float wi2  = W_ih[j * I_ + 2];
    const float bias = b_ih[j] + b_hh[j];

    hbuf[0][half][j] = h0[j];
    HALF_BAR(bar);

    const float* inb  = inputs + (size_t)b * T_ * I_;
    float*       hout = hiddens + (size_t)b * T_ * H_;

    float x0 = inb[0], x1 = inb[1], x2 = inb[2];

    int cur = 0;
#pragma unroll 1
    for (int t = 0; t < T_; ++t) {
        float acc = fmaf(x0, wi0, fmaf(x1, wi1, fmaf(x2, wi2, bias)));

        // prefetch next x (off the critical tail)
        {
            const int tn = (t + 1 < T_) ? (t + 1) : (T_ - 1);
            const float* nx = inb + tn * I_;
            x0 = nx[0]; x1 = nx[1]; x2 = nx[2];
        }

        // h . W_hh[j,:] — broadcast smem reads, 4 independent FMA chains
        float a0 = 0.f, a1 = 0.f, a2 = 0.f, a3 = 0.f;
        const float4* h4 = reinterpret_cast<const float4*>(hbuf[cur][half]);
#pragma unroll
        for (int kk = 0; kk < H_ / 4; ++kk) {
            float4 hv = h4[kk];
            a0 = fmaf(hv.x, w[4 * kk + 0], a0);
            a1 = fmaf(hv.y, w[4 * kk + 1], a1);
            a2 = fmaf(hv.z, w[4 * kk + 2], a2);
            a3 = fmaf(hv.w, w[4 * kk + 3], a3);
        }
        acc += (a0 + a1) + (a2 + a3);

        const float hn = fast_tanh(acc);
        const int nxt = cur ^ 1;
        hbuf[nxt][half][j] = hn;     // other buffer: no WAR on readers
        hout[t * H_ + j] = hn;       // coalesced, fire-and-forget
        cur = nxt;
        HALF_BAR(bar);
    }
}

// ---------------------------------------------------------------------------
// Output projection: 4 rows per warp (best measured config: ~30us).
// ---------------------------------------------------------------------------
#define ROWS_PER_WARP 4

__global__ void __launch_bounds__(256)
rnn_outproj_kernel(const float* __restrict__ hiddens, // [B*T, H]
                   const float* __restrict__ W_out,   // [O, H]
                   const float* __restrict__ b_out,   // [O]
                   float* __restrict__ out)           // [B*T, O]
{
    const int warp = (blockIdx.x * blockDim.x + threadIdx.x) >> 5;
    const int lane = threadIdx.x & 31;
    const int row0 = warp * ROWS_PER_WARP;
    if (row0 >= B_ * T_) return;

    const float4 w0 = reinterpret_cast<const float4*>(W_out + 0 * H_)[lane];
    const float4 w1 = reinterpret_cast<const float4*>(W_out + 1 * H_)[lane];
    const float4 w2 = reinterpret_cast<const float4*>(W_out + 2 * H_)[lane];
    const float bo0 = b_out[0], bo1 = b_out[1], bo2 = b_out[2];

    float4 hv[ROWS_PER_WARP];
#pragma unroll
    for (int r = 0; r < ROWS_PER_WARP; ++r)
        hv[r] = reinterpret_cast<const float4*>(hiddens + (size_t)(row0 + r) * H_)[lane];

#pragma unroll
    for (int r = 0; r < ROWS_PER_WARP; ++r) {
        float s0 = hv[r].x * w0.x + hv[r].y * w0.y + hv[r].z * w0.z + hv[r].w * w0.w;
        float s1 = hv[r].x * w1.x + hv[r].y * w1.y + hv[r].z * w1.z + hv[r].w * w1.w;
        float s2 = hv[r].x * w2.x + hv[r].y * w2.y + hv[r].z * w2.z + hv[r].w * w2.w;
#pragma unroll
        for (int off = 16; off > 0; off >>= 1) {
            s0 += __shfl_down_sync(0xffffffffu, s0, off);
            s1 += __shfl_down_sync(0xffffffffu, s1, off);
            s2 += __shfl_down_sync(0xffffffffu, s2, off);
        }
        if (lane == 0) {
            float* o = out + (size_t)(row0 + r) * O_;
            o[0] = s0 + bo0;
            o[1] = s1 + bo1;
            o[2] = s2 + bo2;
        }
    }
}

// ---------------------------------------------------------------------------
// kernel_launch
// ---------------------------------------------------------------------------
extern "C" void kernel_launch(void* const* d_in, const int* in_sizes, int n_in,
                              void* d_out, int out_size)
{
    const float* inputs = (const float*)d_in[0];
    const float* W_ih   = (const float*)d_in[1];
    const float* W_hh   = (const float*)d_in[2];
    const float* b_ih   = (const float*)d_in[3];
    const float* b_hh   = (const float*)d_in[4];
    const float* h0     = (const float*)d_in[5];
    const float* W_out  = (const float*)d_in[6];
    const float* b_out  = (const float*)d_in[7];

    float* out     = (float*)d_out;                        // [B,T,O]
    float* hiddens = (float*)d_out + (size_t)B_ * T_ * O_; // [B,T,H]

    rnn_recurrent_kernel<<<B_ / 2, 256>>>(inputs, W_ih, W_hh, b_ih, b_hh, h0, hiddens);

    const int rows = B_ * T_;
    const int rows_per_block = (256 / 32) * ROWS_PER_WARP;
    const int blocks = (rows + rows_per_block - 1) / rows_per_block;
    rnn_outproj_kernel<<<blocks, 256>>>(hiddens, W_out, b_out, out);
}

// round 6
// speedup vs baseline: 1.1719x; 1.1364x over previous
#include <cuda_runtime.h>
#include <math.h>

// Problem constants
#define B_  256
#define T_  1024
#define I_  3
#define H_  128
#define O_  3

#define RING 16   // h-state ring depth (2 groups of 8 steps)

// ---------------------------------------------------------------------------
// Fast tanh: tanh(x) = 1 - 2/(1 + e^{2x}) via ex2.approx + rcp.approx.
// Rel err ~1e-6 (measured end-to-end through the recurrence: 5e-7).
// ---------------------------------------------------------------------------
__device__ __forceinline__ float fast_tanh(float x) {
    float u = fminf(x * 2.885390081777927f, 80.0f);   // 2*log2(e)*x, clamped
    float e;
    asm("ex2.approx.f32 %0, %1;" : "=f"(e) : "f"(u));
    float rd;
    asm("rcp.approx.f32 %0, %1;" : "=f"(rd) : "f"(1.0f + e));
    return fmaf(-2.0f, rd, 1.0f);
}

// ---------------------------------------------------------------------------
// Fused RNN kernel (R3 core + inline bulk output projection).
// One block per batch, one thread per hidden unit, W_hh row in registers.
// Hidden state in a 16-deep smem ring: step t reads slot (t-1)&15, writes
// slot t&15. Every 8 steps, all 4 warps dot-product the 8 completed rows
// (2 rows per warp -> SMSP-balanced) against W_out and write out[b][t].
// Ring slots read by the burst (t-8..t-1) are disjoint from slots written
// during steps t..t+7, so no extra barriers are needed.
// ---------------------------------------------------------------------------
__global__ void __launch_bounds__(H_, 2)
rnn_fused_kernel(const float* __restrict__ inputs,   // [B, T, I]
                 const float* __restrict__ W_ih,     // [H, I]
                 const float* __restrict__ W_hh,     // [H, H]
                 const float* __restrict__ b_ih,     // [H]
                 const float* __restrict__ b_hh,     // [H]
                 const float* __restrict__ h0,       // [1, H]
                 const float* __restrict__ W_out,    // [O, H]
                 const float* __restrict__ b_out,    // [O]
                 float* __restrict__ out,            // [B, T, O]
                 float* __restrict__ hiddens)        // [B, T, H]
{
    const int b    = blockIdx.x;
    const int j    = threadIdx.x;
    const int lane = j & 31;
    const int warp = j >> 5;

    __shared__ float ring[RING][H_];

    // W_hh row j -> 128 registers
    float w[H_];
    const float4* wrow = reinterpret_cast<const float4*>(W_hh + j * H_);
#pragma unroll
    for (int kk = 0; kk < H_ / 4; ++kk) {
        float4 v = wrow[kk];
        w[4 * kk + 0] = v.x;
        w[4 * kk + 1] = v.y;
        w[4 * kk + 2] = v.z;
        w[4 * kk + 3] = v.w;
    }

    const float wi0  = W_ih[j * I_ + 0];
    const float wi1  = W_ih[j * I_ + 1];
    const float wi2  = W_ih[j * I_ + 2];
    const float bias = b_ih[j] + b_hh[j];

    // Output-projection weights: lane l covers h[4l..4l+3]
    const float4 o0 = reinterpret_cast<const float4*>(W_out + 0 * H_)[lane];
    const float4 o1 = reinterpret_cast<const float4*>(W_out + 1 * H_)[lane];
    const float4 o2 = reinterpret_cast<const float4*>(W_out + 2 * H_)[lane];
    const float bo0 = b_out[0], bo1 = b_out[1], bo2 = b_out[2];

    ring[RING - 1][j] = h0[j];   // slot (0-1)&15
    __syncthreads();

    const float* inb  = inputs + (size_t)b * T_ * I_;
    float*       hout = hiddens + (size_t)b * T_ * H_;
    float*       ob   = out + (size_t)b * T_ * O_;

    float x0 = inb[0], x1 = inb[1], x2 = inb[2];

#pragma unroll 1
    for (int t = 0; t < T_; ++t) {
        // ---- bulk output projection for the previous 8-step group ----
        if ((t & 7) == 0 && t >= 8) {
            const int base = t - 8;
#pragma unroll
            for (int r2 = 0; r2 < 2; ++r2) {
                const int row = base + 2 * warp + r2;
                const float4 hv = reinterpret_cast<const float4*>(ring[row & (RING - 1)])[lane];
                float s0 = hv.x * o0.x + hv.y * o0.y + hv.z * o0.z + hv.w * o0.w;
                float s1 = hv.x * o1.x + hv.y * o1.y + hv.z * o1.z + hv.w * o1.w;
                float s2 = hv.x * o2.x + hv.y * o2.y + hv.z * o2.z + hv.w * o2.w;
#pragma unroll
                for (int off = 16; off > 0; off >>= 1) {
                    s0 += __shfl_down_sync(0xffffffffu, s0, off);
                    s1 += __shfl_down_sync(0xffffffffu, s1, off);
                    s2 += __shfl_down_sync(0xffffffffu, s2, off);
                }
                if (lane == 0) {
                    float* o = ob + (size_t)row * O_;
                    o[0] = s0 + bo0;
                    o[1] = s1 + bo1;
                    o[2] = s2 + bo2;
                }
            }
        }

        // ---- recurrence step ----
        float acc = fmaf(x0, wi0, fmaf(x1, wi1, fmaf(x2, wi2, bias)));

        // prefetch next x (off the critical tail)
        {
            const int tn = (t + 1 < T_) ? (t + 1) : (T_ - 1);
            const float* nx = inb + tn * I_;
            x0 = nx[0]; x1 = nx[1]; x2 = nx[2];
        }

        float a0 = 0.f, a1 = 0.f, a2 = 0.f, a3 = 0.f;
        const float4* h4 = reinterpret_cast<const float4*>(ring[(t + RING - 1) & (RING - 1)]);
#pragma unroll
        for (int kk = 0; kk < H_ / 4; ++kk) {
            float4 hv = h4[kk];
            a0 = fmaf(hv.x, w[4 * kk + 0], a0);
            a1 = fmaf(hv.y, w[4 * kk + 1], a1);
            a2 = fmaf(hv.z, w[4 * kk + 2], a2);
            a3 = fmaf(hv.w, w[4 * kk + 3], a3);
        }
        acc += (a0 + a1) + (a2 + a3);

        const float hn = fast_tanh(acc);
        ring[t & (RING - 1)][j] = hn;
        hout[t * H_ + j] = hn;       // coalesced, fire-and-forget
        __syncthreads();
    }

    // ---- final group: rows T-8 .. T-1 ----
    {
        const int base = T_ - 8;
#pragma unroll
        for (int r2 = 0; r2 < 2; ++r2) {
            const int row = base + 2 * warp + r2;
            const float4 hv = reinterpret_cast<const float4*>(ring[row & (RING - 1)])[lane];
            float s0 = hv.x * o0.x + hv.y * o0.y + hv.z * o0.z + hv.w * o0.w;
            float s1 = hv.x * o1.x + hv.y * o1.y + hv.z * o1.z + hv.w * o1.w;
            float s2 = hv.x * o2.x + hv.y * o2.y + hv.z * o2.z + hv.w * o2.w;
#pragma unroll
            for (int off = 16; off > 0; off >>= 1) {
                s0 += __shfl_down_sync(0xffffffffu, s0, off);
                s1 += __shfl_down_sync(0xffffffffu, s1, off);
                s2 += __shfl_down_sync(0xffffffffu, s2, off);
            }
            if (lane == 0) {
                float* o = ob + (size_t)row * O_;
                o[0] = s0 + bo0;
                o[1] = s1 + bo1;
                o[2] = s2 + bo2;
            }
        }
    }
}

// ---------------------------------------------------------------------------
// kernel_launch
// ---------------------------------------------------------------------------
extern "C" void kernel_launch(void* const* d_in, const int* in_sizes, int n_in,
                              void* d_out, int out_size)
{
    const float* inputs = (const float*)d_in[0];
    const float* W_ih   = (const float*)d_in[1];
    const float* W_hh   = (const float*)d_in[2];
    const float* b_ih   = (const float*)d_in[3];
    const float* b_hh   = (const float*)d_in[4];
    const float* h0     = (const float*)d_in[5];
    const float* W_out  = (const float*)d_in[6];
    const float* b_out  = (const float*)d_in[7];

    float* out     = (float*)d_out;                        // [B,T,O]
    float* hiddens = (float*)d_out + (size_t)B_ * T_ * O_; // [B,T,H]

    rnn_fused_kernel<<<B_, H_>>>(inputs, W_ih, W_hh, b_ih, b_hh, h0,
                                 W_out, b_out, out, hiddens);
}

// round 7
// speedup vs baseline: 1.1884x; 1.0141x over previous
#include <cuda_runtime.h>

// Problem constants
#define B_  256
#define T_  1024
#define I_  3
#define H_  128
#define O_  3

#define CHUNK     32                 // steps per progress publish
#define NWORKERS  40                 // outproj worker blocks
#define GRID      (B_ + NWORKERS)    // 296 = 148 SMs x 2 blocks

// Progress flags: recurrent block b publishes highest finished step count.
__device__ int g_progress[B_];

// ---------------------------------------------------------------------------
// Fast tanh: tanh(x) = 1 - 2/(1 + e^{2x}) via ex2.approx + rcp.approx.
// Proven end-to-end rel err ~5e-7 over the 1024-step recurrence.
// ---------------------------------------------------------------------------
__device__ __forceinline__ float fast_tanh(float x) {
    float u = fminf(x * 2.885390081777927f, 80.0f);
    float e;
    asm("ex2.approx.f32 %0, %1;" : "=f"(e) : "f"(u));
    float rd;
    asm("rcp.approx.f32 %0, %1;" : "=f"(rd) : "f"(1.0f + e));
    return fmaf(-2.0f, rd, 1.0f);
}

__device__ __forceinline__ int ld_acquire_gpu(const int* p) {
    int v;
    asm volatile("ld.acquire.gpu.b32 %0, [%1];" : "=r"(v) : "l"(p) : "memory");
    return v;
}

// ---------------------------------------------------------------------------
// Reset kernel: zero the progress flags (stream-ordered before the main one).
// ---------------------------------------------------------------------------
__global__ void reset_kernel() {
    if (threadIdx.x < B_) g_progress[threadIdx.x] = 0;
}

// ---------------------------------------------------------------------------
// Fused kernel, two block roles:
//   blockIdx < 256 : recurrent block (R3 core, untouched hot loop) + a
//                    progress publish every CHUNK steps.
//   blockIdx >= 256: worker block streaming the output projection of
//                    finished timesteps (reads are L2-hot).
// ---------------------------------------------------------------------------
__global__ void __launch_bounds__(H_, 2)
rnn_kernel(const float* __restrict__ inputs,   // [B, T, I]
           const float* __restrict__ W_ih,     // [H, I]
           const float* __restrict__ W_hh,     // [H, H]
           const float* __restrict__ b_ih,     // [H]
           const float* __restrict__ b_hh,     // [H]
           const float* __restrict__ h0,       // [1, H]
           const float* __restrict__ W_out,    // [O, H]
           const float* __restrict__ b_out,    // [O]
           float* __restrict__ out,            // [B, T, O]
           float* __restrict__ hiddens)        // [B, T, H]
{
    if (blockIdx.x < B_) {
        // ================= recurrent block =================
        const int b = blockIdx.x;
        const int j = threadIdx.x;

        __shared__ float hbuf[2][H_];

        float w[H_];
        const float4* wrow = reinterpret_cast<const float4*>(W_hh + j * H_);
#pragma unroll
        for (int kk = 0; kk < H_ / 4; ++kk) {
            float4 v = wrow[kk];
            w[4 * kk + 0] = v.x;
            w[4 * kk + 1] = v.y;
            w[4 * kk + 2] = v.z;
            w[4 * kk + 3] = v.w;
        }

        const float wi0  = W_ih[j * I_ + 0];
        const float wi1  = W_ih[j * I_ + 1];
        const float wi2  = W_ih[j * I_ + 2];
        const float bias = b_ih[j] + b_hh[j];

        hbuf[0][j] = h0[j];
        __syncthreads();

        const float* inb  = inputs + (size_t)b * T_ * I_;
        float*       hout = hiddens + (size_t)b * T_ * H_;

        float x0 = inb[0], x1 = inb[1], x2 = inb[2];

        int cur = 0;
#pragma unroll 1
        for (int t = 0; t < T_; ++t) {
            float acc = fmaf(x0, wi0, fmaf(x1, wi1, fmaf(x2, wi2, bias)));

            {
                const int tn = (t + 1 < T_) ? (t + 1) : (T_ - 1);
                const float* nx = inb + tn * I_;
                x0 = nx[0]; x1 = nx[1]; x2 = nx[2];
            }

            float a0 = 0.f, a1 = 0.f, a2 = 0.f, a3 = 0.f;
            const float4* h4 = reinterpret_cast<const float4*>(hbuf[cur]);
#pragma unroll
            for (int kk = 0; kk < H_ / 4; ++kk) {
                float4 hv = h4[kk];
                a0 = fmaf(hv.x, w[4 * kk + 0], a0);
                a1 = fmaf(hv.y, w[4 * kk + 1], a1);
                a2 = fmaf(hv.z, w[4 * kk + 2], a2);
                a3 = fmaf(hv.w, w[4 * kk + 3], a3);
            }
            acc += (a0 + a1) + (a2 + a3);

            const float hn = fast_tanh(acc);
            const int nxt = cur ^ 1;
            hbuf[nxt][j] = hn;
            hout[t * H_ + j] = hn;
            cur = nxt;
            __syncthreads();

            // publish progress every CHUNK steps (after the barrier: all
            // threads' hout stores for steps <= t are issued)
            if (((t + 1) & (CHUNK - 1)) == 0) {
                __threadfence();
                if (j == 0) atomicExch(&g_progress[b], t + 1);
            }
        }
    } else {
        // ================= worker block: streamed output projection =========
        const int w    = blockIdx.x - B_;    // 0..39
        const int tid  = threadIdx.x;
        const int lane = tid & 31;
        const int warp = tid >> 5;

        const float4 w0 = reinterpret_cast<const float4*>(W_out + 0 * H_)[lane];
        const float4 w1 = reinterpret_cast<const float4*>(W_out + 1 * H_)[lane];
        const float4 w2 = reinterpret_cast<const float4*>(W_out + 2 * H_)[lane];
        const float bo0 = b_out[0], bo1 = b_out[1], bo2 = b_out[2];

        // chunks outer, batches inner: all recurrent blocks advance in sync
#pragma unroll 1
        for (int c = 0; c < T_ / CHUNK; ++c) {
            const int t0     = c * CHUNK;
            const int target = t0 + CHUNK;
#pragma unroll 1
            for (int b = w; b < B_; b += NWORKERS) {
                // wait until this batch's chunk is complete
                while (ld_acquire_gpu(&g_progress[b]) < target)
                    __nanosleep(200);

                // 32 rows: warp handles 8 (two groups of 4)
#pragma unroll 1
                for (int g = 0; g < 2; ++g) {
                    const size_t rowbase = (size_t)b * T_ + t0 + warp * 8 + g * 4;

                    float4 hv[4];
#pragma unroll
                    for (int r = 0; r < 4; ++r)
                        hv[r] = reinterpret_cast<const float4*>(
                                    hiddens + (rowbase + r) * H_)[lane];

#pragma unroll
                    for (int r = 0; r < 4; ++r) {
                        float s0 = hv[r].x * w0.x + hv[r].y * w0.y + hv[r].z * w0.z + hv[r].w * w0.w;
                        float s1 = hv[r].x * w1.x + hv[r].y * w1.y + hv[r].z * w1.z + hv[r].w * w1.w;
                        float s2 = hv[r].x * w2.x + hv[r].y * w2.y + hv[r].z * w2.z + hv[r].w * w2.w;
#pragma unroll
                        for (int off = 16; off > 0; off >>= 1) {
                            s0 += __shfl_down_sync(0xffffffffu, s0, off);
                            s1 += __shfl_down_sync(0xffffffffu, s1, off);
                            s2 += __shfl_down_sync(0xffffffffu, s2, off);
                        }
                        if (lane == 0) {
                            float* o = out + (rowbase + r) * O_;
                            o[0] = s0 + bo0;
                            o[1] = s1 + bo1;
                            o[2] = s2 + bo2;
                        }
                    }
                }
            }
        }
    }
}

// ---------------------------------------------------------------------------
// kernel_launch
// ---------------------------------------------------------------------------
extern "C" void kernel_launch(void* const* d_in, const int* in_sizes, int n_in,
                              void* d_out, int out_size)
{
    const float* inputs = (const float*)d_in[0];
    const float* W_ih   = (const float*)d_in[1];
    const float* W_hh   = (const float*)d_in[2];
    const float* b_ih   = (const float*)d_in[3];
    const float* b_hh   = (const float*)d_in[4];
    const float* h0     = (const float*)d_in[5];
    const float* W_out  = (const float*)d_in[6];
    const float* b_out  = (const float*)d_in[7];

    float* out     = (float*)d_out;                        // [B,T,O]
    float* hiddens = (float*)d_out + (size_t)B_ * T_ * O_; // [B,T,H]

    reset_kernel<<<1, 256>>>();
    rnn_kernel<<<GRID, H_>>>(inputs, W_ih, W_hh, b_ih, b_hh, h0,
                             W_out, b_out, out, hiddens);
}